// round 8
// baseline (speedup 1.0000x reference)
#include <cuda_runtime.h>
#include <cuda_bf16.h>
#include <math.h>
#include <stdint.h>

#define N_TOK 16384
#define C_DIM 768
#define I_DIM 1536
#define E_EXP 16
#define E_ALL 17
#define SLOTS (3*N_TOK)
#define TILE_B 16384
#define STAGE_F (6*TILE_B)
#define STAGE_D (4*TILE_B)
#define SMEM_F (2*STAGE_F + 1024)
#define SMEM_D (2*STAGE_D + 1024)

// ---------------- static device scratch ----------------
__device__ int   g_counts[E_EXP];
__device__ int   g_offsets[E_EXP];
__device__ int   g_cursor[E_EXP];
__device__ int   g_re[N_TOK*2];
__device__ float g_rw[N_TOK*2];
__device__ int   g_ids[SLOTS];
__device__ float g_wt[SLOTS];
__device__ int   g_slot_of[N_TOK*2];

__device__ __nv_bfloat16 g_xh[(size_t)N_TOK*C_DIM];
__device__ __nv_bfloat16 g_xl[(size_t)N_TOK*C_DIM];
__device__ __nv_bfloat16 g_gh[(size_t)E_ALL*I_DIM*C_DIM];  // [(e*I+n)*C+k]
__device__ __nv_bfloat16 g_gl[(size_t)E_ALL*I_DIM*C_DIM];
__device__ __nv_bfloat16 g_uh[(size_t)E_ALL*I_DIM*C_DIM];
__device__ __nv_bfloat16 g_ul[(size_t)E_ALL*I_DIM*C_DIM];
__device__ __nv_bfloat16 g_dh[(size_t)E_ALL*C_DIM*I_DIM];  // [(e*C+n)*I+k]
__device__ __nv_bfloat16 g_dl[(size_t)E_ALL*C_DIM*I_DIM];
__device__ __nv_bfloat16 g_hh[(size_t)SLOTS*I_DIM];
__device__ __nv_bfloat16 g_hl[(size_t)SLOTS*I_DIM];
__device__ float g_O[(size_t)SLOTS*C_DIM];

// ---------------- PTX helpers (base ISA only) ----------------
__device__ __forceinline__ uint32_t smem_u32(const void* p){
    uint32_t a;
    asm("{ .reg .u64 t; cvta.to.shared.u64 t, %1; cvt.u32.u64 %0, t; }" : "=r"(a) : "l"(p));
    return a;
}
__device__ __forceinline__ void cp_row(uint32_t sbase, const void* src, int t){
    #pragma unroll
    for (int ch = 0; ch < 8; ch++){
        uint32_t off = (uint32_t)t*128u + (uint32_t)ch*16u;
        uint32_t dst = sbase + (off ^ ((off >> 3) & 0x70u));
        asm volatile("cp.async.cg.shared.global [%0], [%1], 16;"
            :: "r"(dst), "l"((const char*)src + ch*16) : "memory");
    }
}
__device__ __forceinline__ void cp_commit(){ asm volatile("cp.async.commit_group;" ::: "memory"); }
__device__ __forceinline__ void cp_wait1(){ asm volatile("cp.async.wait_group 1;" ::: "memory"); }
__device__ __forceinline__ void cp_wait0(){ asm volatile("cp.async.wait_group 0;" ::: "memory"); }

__device__ __forceinline__ void ldsm4(uint32_t* r, uint32_t addr){
    asm volatile("ldmatrix.sync.aligned.m8n8.x4.shared.b16 {%0,%1,%2,%3}, [%4];"
        : "=r"(r[0]), "=r"(r[1]), "=r"(r[2]), "=r"(r[3]) : "r"(addr));
}
__device__ __forceinline__ void hmma(float* d, const uint32_t* a, const uint32_t* b){
    asm volatile("mma.sync.aligned.m16n8k16.row.col.f32.bf16.bf16.f32 "
        "{%0,%1,%2,%3}, {%4,%5,%6,%7}, {%8,%9}, {%0,%1,%2,%3};"
        : "+f"(d[0]), "+f"(d[1]), "+f"(d[2]), "+f"(d[3])
        : "r"(a[0]), "r"(a[1]), "r"(a[2]), "r"(a[3]), "r"(b[0]), "r"(b[1]));
}

// ---------------- setup kernels ----------------
__global__ void init_kernel(){ if (threadIdx.x < E_EXP) g_counts[threadIdx.x] = 0; }

__global__ void router_kernel(const float* __restrict__ x, const float* __restrict__ wgate,
                              const float* __restrict__ bias){
    int warp = (blockIdx.x * blockDim.x + threadIdx.x) >> 5;
    int lane = threadIdx.x & 31;
    if (warp >= N_TOK) return;
    float acc = 0.f;
    if (lane < E_EXP){
        const float* xr = x + (size_t)warp * C_DIM;
        #pragma unroll 8
        for (int c = 0; c < C_DIM; c++) acc = fmaf(xr[c], wgate[c*E_EXP + lane], acc);
        acc += bias[lane];
    }
    float l0 = -1e30f, l1 = -1e30f; int i0 = 0, i1 = 0;
    #pragma unroll
    for (int e = 0; e < E_EXP; e++){
        float v = __shfl_sync(0xffffffffu, acc, e);
        if (v > l0)      { l1 = l0; i1 = i0; l0 = v; i0 = e; }
        else if (v > l1) { l1 = v;  i1 = e; }
    }
    if (lane == 0){
        float w0 = 1.f / (1.f + __expf(l1 - l0));
        g_re[warp*2+0] = i0; g_rw[warp*2+0] = w0;
        g_re[warp*2+1] = i1; g_rw[warp*2+1] = 1.f - w0;
        atomicAdd(&g_counts[i0], 1); atomicAdd(&g_counts[i1], 1);
    }
}

__global__ void scan_kernel(){
    if (threadIdx.x == 0){
        int off = 0;
        for (int e = 0; e < E_EXP; e++){ g_offsets[e] = off; g_cursor[e] = off; off += g_counts[e]; }
    }
}

__global__ void fill_kernel(){
    int t = blockIdx.x * blockDim.x + threadIdx.x;
    if (t >= N_TOK) return;
    #pragma unroll
    for (int s = 0; s < 2; s++){
        int e = g_re[t*2+s];
        int pos = atomicAdd(&g_cursor[e], 1);
        g_ids[pos] = t; g_wt[pos] = g_rw[t*2+s]; g_slot_of[t*2+s] = pos;
    }
    g_ids[2*N_TOK + t] = t; g_wt[2*N_TOK + t] = 1.f;
}

__global__ void split_x_kernel(const float* __restrict__ x){
    size_t i = (size_t)blockIdx.x * blockDim.x + threadIdx.x;
    if (i >= (size_t)N_TOK*C_DIM) return;
    float v = x[i];
    __nv_bfloat16 h = __float2bfloat16(v);
    g_xh[i] = h; g_xl[i] = __float2bfloat16(v - __bfloat162float(h));
}

// split + transpose: W (per expert (K,N) row-major) -> out[(e*N+n)*K + k]
__global__ void split_T_kernel(const float* __restrict__ W, int which, int ebase, int K, int N){
    __shared__ float t[32][33];
    int e = ebase + blockIdx.z;
    const float* Win = W + (size_t)blockIdx.z * K * N;
    int n0 = blockIdx.x*32, k0 = blockIdx.y*32;
    int tx = threadIdx.x, ty = threadIdx.y;   // (32,8)
    #pragma unroll
    for (int i = 0; i < 4; i++)
        t[ty + i*8][tx] = Win[(size_t)(k0 + ty + i*8)*N + n0 + tx];
    __syncthreads();
    __nv_bfloat16 *oh, *ol;
    if (which == 0){ oh = g_gh; ol = g_gl; }
    else if (which == 1){ oh = g_uh; ol = g_ul; }
    else { oh = g_dh; ol = g_dl; }
    #pragma unroll
    for (int i = 0; i < 4; i++){
        int n = n0 + ty + i*8;
        float v = t[tx][ty + i*8];
        size_t o = ((size_t)e*N + n)*K + k0 + tx;
        __nv_bfloat16 h = __float2bfloat16(v);
        oh[o] = h; ol[o] = __float2bfloat16(v - __bfloat162float(h));
    }
}

// ---------------- fused gate+up HMMA kernel ----------------
// CTA: 512 thr (16 warps, 4x4 warp grid, warp tile 32x32), CTA tile 128x128,
// K-chunk 64 bf16 (128B SW128 rows), double buffered cp.async.
__global__ void __launch_bounds__(512) fused_gateup_kernel(){
    int z = blockIdx.z, cnt, base;
    if (z == E_EXP){ cnt = N_TOK; base = 2*N_TOK; }
    else           { cnt = g_counts[z]; base = g_offsets[z]; }
    int rb = blockIdx.y;
    if (rb*128 >= cnt) return;
    int n0 = blockIdx.x * 128;

    extern __shared__ char smem[];
    uint32_t sb = (smem_u32(smem) + 1023u) & ~1023u;
    int tid = threadIdx.x, lane = tid & 31, wid = tid >> 5;
    int warp_m = wid >> 2, warp_n = wid & 3;   // 4 x 4

    // loader: 768 rows over 512 threads (1-2 rows each)
    const char* lsrc[2]; uint32_t ltile[2]; int lrow[2]; bool lval[2];
    #pragma unroll
    for (int j = 0; j < 2; j++){
        int q = tid + j*512;
        lval[j] = q < 768;
        int tile = q >> 7, row = q & 127;
        const char* p = (const char*)g_xh;
        if (lval[j]){
            if (tile < 2){
                int r = rb*128 + row; int rr = r < cnt ? r : cnt - 1;
                int tok = g_ids[base + rr];
                p = (const char*)((tile == 0 ? g_xh : g_xl) + (size_t)tok*C_DIM);
            } else {
                size_t wr = ((size_t)z*I_DIM + n0 + row)*C_DIM;
                const __nv_bfloat16* w = tile==2 ? g_gh : tile==3 ? g_gl : tile==4 ? g_uh : g_ul;
                p = (const char*)(w + wr);
            }
        }
        lsrc[j] = p; ltile[j] = (uint32_t)tile*TILE_B; lrow[j] = row;
    }
    auto load_stage = [&](int s, int kt){
        uint32_t st = sb + (uint32_t)s*STAGE_F;
        #pragma unroll
        for (int j = 0; j < 2; j++)
            if (lval[j]) cp_row(st + ltile[j], lsrc[j] + kt*128, lrow[j]);
        cp_commit();
    };

    // ldmatrix geometry (warp tile 32x32)
    int mat = lane >> 3;
    uint32_t xm = (uint32_t)(lane & 7) << 4;
    uint32_t rA[2], rB[2];
    #pragma unroll
    for (int mt = 0; mt < 2; mt++)
        rA[mt] = (uint32_t)(warp_m*32 + mt*16 + (mat & 1)*8 + (lane & 7)) << 7;
    #pragma unroll
    for (int p = 0; p < 2; p++)
        rB[p] = (uint32_t)(warp_n*32 + p*16 + ((mat >> 1) & 1)*8 + (lane & 7)) << 7;
    uint32_t caK = (uint32_t)((mat >> 1) & 1) * 16;
    uint32_t cbK = (uint32_t)(mat & 1) * 16;

    float ag[2][4][4], au[2][4][4];
    #pragma unroll
    for (int a = 0; a < 2; a++)
        #pragma unroll
        for (int b = 0; b < 4; b++)
            #pragma unroll
            for (int c = 0; c < 4; c++){ ag[a][b][c] = 0.f; au[a][b][c] = 0.f; }

    const int KT = C_DIM/64;   // 12
    load_stage(0, 0);
    load_stage(1, 1);

    for (int kt = 0; kt < KT; kt++){
        if (kt + 1 < KT) cp_wait1(); else cp_wait0();
        __syncthreads();
        uint32_t st = sb + (uint32_t)(kt & 1)*STAGE_F;
        uint32_t Ah = st, Al = st + TILE_B;
        uint32_t Gh = st + 2*TILE_B, Gl = st + 3*TILE_B;
        uint32_t Uh = st + 4*TILE_B, Ul = st + 5*TILE_B;
        #pragma unroll
        for (int ks = 0; ks < 4; ks++){
            uint32_t cA = ((uint32_t)ks*32 + caK) ^ xm;
            uint32_t cB = ((uint32_t)ks*32 + cbK) ^ xm;
            uint32_t fah[2][4], fal[2][4];
            ldsm4(fah[0], Ah + rA[0] + cA); ldsm4(fah[1], Ah + rA[1] + cA);
            ldsm4(fal[0], Al + rA[0] + cA); ldsm4(fal[1], Al + rA[1] + cA);
            uint32_t b0[2][4], b1[2][4];
            // ---- gate ----
            ldsm4(b0[0], Gh + rB[0] + cB); ldsm4(b0[1], Gh + rB[1] + cB);
            ldsm4(b1[0], Gl + rB[0] + cB); ldsm4(b1[1], Gl + rB[1] + cB);
            #pragma unroll
            for (int mt = 0; mt < 2; mt++)   // pass 1: hi*hi
                #pragma unroll
                for (int nt = 0; nt < 4; nt++)
                    hmma(ag[mt][nt], fah[mt], &b0[nt>>1][(nt&1)*2]);
            #pragma unroll
            for (int mt = 0; mt < 2; mt++)   // pass 2: hi*lo
                #pragma unroll
                for (int nt = 0; nt < 4; nt++)
                    hmma(ag[mt][nt], fah[mt], &b1[nt>>1][(nt&1)*2]);
            #pragma unroll
            for (int mt = 0; mt < 2; mt++)   // pass 3: lo*hi
                #pragma unroll
                for (int nt = 0; nt < 4; nt++)
                    hmma(ag[mt][nt], fal[mt], &b0[nt>>1][(nt&1)*2]);
            // ---- up ----
            ldsm4(b0[0], Uh + rB[0] + cB); ldsm4(b0[1], Uh + rB[1] + cB);
            ldsm4(b1[0], Ul + rB[0] + cB); ldsm4(b1[1], Ul + rB[1] + cB);
            #pragma unroll
            for (int mt = 0; mt < 2; mt++)
                #pragma unroll
                for (int nt = 0; nt < 4; nt++)
                    hmma(au[mt][nt], fah[mt], &b0[nt>>1][(nt&1)*2]);
            #pragma unroll
            for (int mt = 0; mt < 2; mt++)
                #pragma unroll
                for (int nt = 0; nt < 4; nt++)
                    hmma(au[mt][nt], fah[mt], &b1[nt>>1][(nt&1)*2]);
            #pragma unroll
            for (int mt = 0; mt < 2; mt++)
                #pragma unroll
                for (int nt = 0; nt < 4; nt++)
                    hmma(au[mt][nt], fal[mt], &b0[nt>>1][(nt&1)*2]);
        }
        __syncthreads();
        if (kt + 2 < KT) load_stage(kt & 1, kt + 2);
    }

    // epilogue: h = silu(g)*u -> bf16 hi/lo planes
    int qr = lane >> 2, qc = (lane & 3)*2;
    #pragma unroll
    for (int mt = 0; mt < 2; mt++)
        #pragma unroll
        for (int h2 = 0; h2 < 2; h2++){
            int gr = rb*128 + warp_m*32 + mt*16 + h2*8 + qr;
            if (gr >= cnt) continue;
            size_t slot = (size_t)base + gr;
            #pragma unroll
            for (int nt = 0; nt < 4; nt++){
                float g0 = ag[mt][nt][h2*2+0], g1 = ag[mt][nt][h2*2+1];
                float u0 = au[mt][nt][h2*2+0], u1 = au[mt][nt][h2*2+1];
                float h0 = (g0 / (1.f + __expf(-g0))) * u0;
                float h1 = (g1 / (1.f + __expf(-g1))) * u1;
                __nv_bfloat16 h0h = __float2bfloat16(h0), h1h = __float2bfloat16(h1);
                __nv_bfloat162 vh; vh.x = h0h; vh.y = h1h;
                __nv_bfloat162 vl;
                vl.x = __float2bfloat16(h0 - __bfloat162float(h0h));
                vl.y = __float2bfloat16(h1 - __bfloat162float(h1h));
                size_t col = (size_t)n0 + warp_n*32 + nt*8 + qc;
                *(__nv_bfloat162*)(g_hh + slot*I_DIM + col) = vh;
                *(__nv_bfloat162*)(g_hl + slot*I_DIM + col) = vl;
            }
        }
}

// ---------------- down-projection HMMA kernel ----------------
__global__ void __launch_bounds__(512) down_proj_kernel(){
    int z = blockIdx.z, cnt, base;
    if (z == E_EXP){ cnt = N_TOK; base = 2*N_TOK; }
    else           { cnt = g_counts[z]; base = g_offsets[z]; }
    int rb = blockIdx.y;
    if (rb*128 >= cnt) return;
    int n0 = blockIdx.x * 128;

    extern __shared__ char smem[];
    uint32_t sb = (smem_u32(smem) + 1023u) & ~1023u;
    int tid = threadIdx.x, lane = tid & 31, wid = tid >> 5;
    int warp_m = wid >> 2, warp_n = wid & 3;

    // loader: 512 rows over 512 threads (exactly 1 each)
    int ltile = tid >> 7, lrow = tid & 127;
    const char* lsrc;
    if (ltile < 2){
        int r = rb*128 + lrow; int rr = r < cnt ? r : cnt - 1;
        lsrc = (const char*)((ltile == 0 ? g_hh : g_hl) + (size_t)(base + rr)*I_DIM);
    } else {
        size_t wr = ((size_t)z*C_DIM + n0 + lrow)*I_DIM;
        lsrc = (const char*)((ltile == 2 ? g_dh : g_dl) + wr);
    }
    uint32_t ltoff = (uint32_t)ltile*TILE_B;
    auto load_stage = [&](int s, int kt){
        uint32_t st = sb + (uint32_t)s*STAGE_D;
        cp_row(st + ltoff, lsrc + kt*128, lrow);
        cp_commit();
    };

    int mat = lane >> 3;
    uint32_t xm = (uint32_t)(lane & 7) << 4;
    uint32_t rA[2], rB[2];
    #pragma unroll
    for (int mt = 0; mt < 2; mt++)
        rA[mt] = (uint32_t)(warp_m*32 + mt*16 + (mat & 1)*8 + (lane & 7)) << 7;
    #pragma unroll
    for (int p = 0; p < 2; p++)
        rB[p] = (uint32_t)(warp_n*32 + p*16 + ((mat >> 1) & 1)*8 + (lane & 7)) << 7;
    uint32_t caK = (uint32_t)((mat >> 1) & 1) * 16;
    uint32_t cbK = (uint32_t)(mat & 1) * 16;

    float ac[2][4][4];
    #pragma unroll
    for (int a = 0; a < 2; a++)
        #pragma unroll
        for (int b = 0; b < 4; b++)
            #pragma unroll
            for (int c = 0; c < 4; c++) ac[a][b][c] = 0.f;

    const int KT = I_DIM/64;   // 24
    load_stage(0, 0);
    load_stage(1, 1);

    for (int kt = 0; kt < KT; kt++){
        if (kt + 1 < KT) cp_wait1(); else cp_wait0();
        __syncthreads();
        uint32_t st = sb + (uint32_t)(kt & 1)*STAGE_D;
        uint32_t Ah = st, Al = st + TILE_B;
        uint32_t Bh = st + 2*TILE_B, Bl = st + 3*TILE_B;
        #pragma unroll
        for (int ks = 0; ks < 4; ks++){
            uint32_t cA = ((uint32_t)ks*32 + caK) ^ xm;
            uint32_t cB = ((uint32_t)ks*32 + cbK) ^ xm;
            uint32_t fah[2][4], fal[2][4];
            ldsm4(fah[0], Ah + rA[0] + cA); ldsm4(fah[1], Ah + rA[1] + cA);
            ldsm4(fal[0], Al + rA[0] + cA); ldsm4(fal[1], Al + rA[1] + cA);
            uint32_t b0[2][4], b1[2][4];
            ldsm4(b0[0], Bh + rB[0] + cB); ldsm4(b0[1], Bh + rB[1] + cB);
            ldsm4(b1[0], Bl + rB[0] + cB); ldsm4(b1[1], Bl + rB[1] + cB);
            #pragma unroll
            for (int mt = 0; mt < 2; mt++)
                #pragma unroll
                for (int nt = 0; nt < 4; nt++)
                    hmma(ac[mt][nt], fah[mt], &b0[nt>>1][(nt&1)*2]);
            #pragma unroll
            for (int mt = 0; mt < 2; mt++)
                #pragma unroll
                for (int nt = 0; nt < 4; nt++)
                    hmma(ac[mt][nt], fah[mt], &b1[nt>>1][(nt&1)*2]);
            #pragma unroll
            for (int mt = 0; mt < 2; mt++)
                #pragma unroll
                for (int nt = 0; nt < 4; nt++)
                    hmma(ac[mt][nt], fal[mt], &b0[nt>>1][(nt&1)*2]);
        }
        __syncthreads();
        if (kt + 2 < KT) load_stage(kt & 1, kt + 2);
    }

    int qr = lane >> 2, qc = (lane & 3)*2;
    #pragma unroll
    for (int mt = 0; mt < 2; mt++)
        #pragma unroll
        for (int h2 = 0; h2 < 2; h2++){
            int gr = rb*128 + warp_m*32 + mt*16 + h2*8 + qr;
            if (gr >= cnt) continue;
            size_t slot = (size_t)base + gr;
            float wt = g_wt[slot];
            #pragma unroll
            for (int nt = 0; nt < 4; nt++){
                float2 v;
                v.x = wt * ac[mt][nt][h2*2+0];
                v.y = wt * ac[mt][nt][h2*2+1];
                size_t col = (size_t)n0 + warp_n*32 + nt*8 + qc;
                *(float2*)(g_O + slot*C_DIM + col) = v;
            }
        }
}

__global__ void combine_kernel(float* __restrict__ out){
    int i = blockIdx.x * blockDim.x + threadIdx.x;
    if (i >= N_TOK*(C_DIM/4)) return;
    int t = i / (C_DIM/4), c = (i % (C_DIM/4)) * 4;
    int s0 = g_slot_of[t*2], s1 = g_slot_of[t*2+1];
    float4 a = *(const float4*)&g_O[(size_t)s0*C_DIM + c];
    float4 b = *(const float4*)&g_O[(size_t)s1*C_DIM + c];
    float4 d = *(const float4*)&g_O[(size_t)(2*N_TOK + t)*C_DIM + c];
    float4 r = make_float4(a.x+b.x+d.x, a.y+b.y+d.y, a.z+b.z+d.z, a.w+b.w+d.w);
    *(float4*)&out[(size_t)t*C_DIM + c] = r;
}

// ---------------- launch ----------------
extern "C" void kernel_launch(void* const* d_in, const int* in_sizes, int n_in,
                              void* d_out, int out_size) {
    const float* x    = (const float*)d_in[0];
    const float* wgt  = (const float*)d_in[1];
    const float* bias = (const float*)d_in[2];
    const float* wg   = (const float*)d_in[3];
    const float* wu   = (const float*)d_in[4];
    const float* wd   = (const float*)d_in[5];
    const float* swg  = (const float*)d_in[6];
    const float* swu  = (const float*)d_in[7];
    const float* swd  = (const float*)d_in[8];
    float* out = (float*)d_out;

    cudaFuncSetAttribute(fused_gateup_kernel, cudaFuncAttributeMaxDynamicSharedMemorySize, SMEM_F);
    cudaFuncSetAttribute(down_proj_kernel,    cudaFuncAttributeMaxDynamicSharedMemorySize, SMEM_D);

    init_kernel<<<1, 32>>>();
    router_kernel<<<(N_TOK*32 + 255)/256, 256>>>(x, wgt, bias);
    scan_kernel<<<1, 1>>>();
    fill_kernel<<<(N_TOK + 255)/256, 256>>>();

    split_x_kernel<<<(N_TOK*C_DIM + 255)/256, 256>>>(x);
    dim3 tb(32, 8);
    split_T_kernel<<<dim3(I_DIM/32, C_DIM/32, E_EXP), tb>>>(wg,  0, 0,  C_DIM, I_DIM);
    split_T_kernel<<<dim3(I_DIM/32, C_DIM/32, 1),     tb>>>(swg, 0, 16, C_DIM, I_DIM);
    split_T_kernel<<<dim3(I_DIM/32, C_DIM/32, E_EXP), tb>>>(wu,  1, 0,  C_DIM, I_DIM);
    split_T_kernel<<<dim3(I_DIM/32, C_DIM/32, 1),     tb>>>(swu, 1, 16, C_DIM, I_DIM);
    split_T_kernel<<<dim3(C_DIM/32, I_DIM/32, E_EXP), tb>>>(wd,  2, 0,  I_DIM, C_DIM);
    split_T_kernel<<<dim3(C_DIM/32, I_DIM/32, 1),     tb>>>(swd, 2, 16, I_DIM, C_DIM);

    fused_gateup_kernel<<<dim3(I_DIM/128, N_TOK/128, E_ALL), 512, SMEM_F>>>();
    down_proj_kernel  <<<dim3(C_DIM/128, N_TOK/128, E_ALL), 512, SMEM_D>>>();
    combine_kernel<<<(N_TOK*(C_DIM/4) + 255)/256, 256>>>(out);
}